// round 16
// baseline (speedup 1.0000x reference)
#include <cuda_runtime.h>
#include <stdint.h>

#define HOPS   3
#define LBL    10
#define DIM    128
#define ROWB   512                      // bytes per node row (128 f32)
#define CHUNK  64                       // nodes per pipeline stage (32 KB)
#define STAGES 3
#define STAGE_BYTES (CHUNK * ROWB)
#define SMEM_STAGE0 1024
#define SMEM_TOTAL  (SMEM_STAGE0 + STAGES * STAGE_BYTES)   // 99328 B -> 2 CTA/SM
#define CONS_WARPS 20                   // 2 consumer warps per label
#define WARPS  (CONS_WARPS + 1)         // + 1 producer
#define THREADS (WARPS * 32)            // 672
#define GRIDX  98                       // per hop; 98*3=294 CTAs = one wave @2 CTA/SM

// Scratch (__device__ globals — zero-initialized at load; the finalizer
// re-zeroes them each run so every graph replay starts from clean scratch).
__device__ float        g_sums[HOPS * LBL * DIM];
__device__ float        g_counts[LBL];
__device__ unsigned int g_done;

// --- PTX helpers -----------------------------------------------------------
__device__ __forceinline__ uint32_t smem_u32(const void* p) {
    uint32_t a;
    asm("{ .reg .u64 t; cvta.to.shared.u64 t, %1; cvt.u32.u64 %0, t; }"
        : "=r"(a) : "l"(p));
    return a;
}
#define MBAR_INIT(addr, cnt) \
    asm volatile("mbarrier.init.shared.b64 [%0], %1;" :: "r"(addr), "r"(cnt) : "memory")
#define MBAR_EXPECT_TX(addr, bytes) \
    asm volatile("mbarrier.arrive.expect_tx.shared.b64 _, [%0], %1;" :: "r"(addr), "r"(bytes) : "memory")
#define MBAR_ARRIVE(addr) \
    asm volatile("mbarrier.arrive.shared.b64 _, [%0];" :: "r"(addr) : "memory")
#define MBAR_WAIT(addr, parity) do {                                          \
    uint32_t _m = (addr); uint32_t _p = (parity); uint32_t _d;                \
    asm volatile("{ .reg .pred p;\n\t"                                        \
        "mbarrier.try_wait.parity.acquire.cta.shared::cta.b64 p, [%1], %2;\n\t"\
        "selp.b32 %0, 1, 0, p; }" : "=r"(_d) : "r"(_m), "r"(_p) : "memory");  \
    if (!_d) {                                                                \
        asm volatile("{ .reg .pred P1;\n\t"                                   \
            "W%=:\n\t"                                                        \
            "mbarrier.try_wait.parity.acquire.cta.shared::cta.b64 P1, [%0], %1, 0x989680;\n\t" \
            "@P1 bra.uni D%=;\n\t"                                            \
            "bra.uni W%=;\n\t"                                                \
            "D%=: }" :: "r"(_m), "r"(_p) : "memory");                         \
    }                                                                         \
} while (0)
// 1D bulk copy global->shared (SASS: UBLKCP), complete_tx to mbarrier.
#define BULK_G2S(dst, src, bytes, mbar) \
    asm volatile("cp.async.bulk.shared::cluster.global.mbarrier::complete_tx::bytes [%0], [%1], %2, [%3];" \
        :: "r"(dst), "l"(src), "r"(bytes), "r"(mbar) : "memory")

__device__ __forceinline__ void lds128(uint32_t a, float& x, float& y, float& z, float& w) {
    asm volatile("ld.shared.v4.f32 {%0,%1,%2,%3}, [%4];"
                 : "=f"(x), "=f"(y), "=f"(z), "=f"(w) : "r"(a));
}

// Consume all set bits of mask: batched LDS.128 row reads + register FADD.
__device__ __forceinline__ void eat_mask(unsigned mask, uint32_t rowbase, int lane,
                                         float& ax, float& ay, float& az, float& aw) {
    while (mask) {
        uint32_t a[4]; int nb = 0;
#pragma unroll
        for (int k = 0; k < 4; k++) {
            if (mask) { int idx = __ffs(mask) - 1; mask &= mask - 1;
                        a[k] = rowbase + idx * ROWB + lane * 16; nb = k + 1; }
        }
        float x[4], y[4], z[4], w[4];
#pragma unroll
        for (int k = 0; k < 4; k++) if (k < nb) lds128(a[k], x[k], y[k], z[k], w[k]);
#pragma unroll
        for (int k = 0; k < 4; k++) if (k < nb) { ax += x[k]; ay += y[k]; az += z[k]; aw += w[k]; }
    }
}

// ---------------------------------------------------------------------------
// Single fused kernel. blockIdx.y = hop. Warp 20 = producer (cp.async.bulk
// ring, 3 stages x 32 KB, 2 CTA/SM). Warps 0-19 = consumers: warp w owns
// label w>>1, half (w&1) of each chunk -> max rows per warp ~7 (was ~13),
// halving the consumer critical path that gates chunk cadence.
// Last block (global ticket) finalizes output and re-zeroes scratch.
// ---------------------------------------------------------------------------
__global__ void __launch_bounds__(THREADS, 2)
accumulate_kernel(const float* __restrict__ emb,
                  const void*  __restrict__ labels_raw,
                  int N,
                  const float* __restrict__ weight,
                  float* __restrict__ out,
                  int totalBlocks) {
    extern __shared__ char smem[];
    const uint32_t sb = smem_u32(smem);
    __shared__ int s_not64;
    __shared__ unsigned int s_ticket;

    const int tid  = threadIdx.x;
    const int warp = tid >> 5;
    const int lane = tid & 31;
    const int hop  = blockIdx.y;

    // mbarriers: full(s)=sb+s*16, empty(s)=sb+s*16+8
    if (tid == 0) {
        for (int s = 0; s < STAGES; s++) {
            MBAR_INIT(sb + s * 16,     1u);              // full: tx-based
            MBAR_INIT(sb + s * 16 + 8, CONS_WARPS);      // empty: 20 consumer warps
        }
        s_not64 = 0;
    }
    __syncthreads();

    // labels dtype detection: int64 labels (0..9, LE) => odd 32-bit words all 0.
    {
        const int* l32 = reinterpret_cast<const int*>(labels_raw);
        int nscan = N / 2; if (nscan > 4096) nscan = 4096;
        for (int j = tid; j < nscan; j += THREADS)
            if (l32[2 * j + 1] != 0) s_not64 = 1;
    }
    __syncthreads();
    const bool is64 = (s_not64 == 0);

    const int CHUNKS = (N + CHUNK - 1) / CHUNK;

    if (warp == CONS_WARPS) {
        // ---------------- producer ----------------
        if (lane == 0) {
            int stage = 0, phase = 1;   // first STAGES empty-waits pass immediately
            const char* hop_base = reinterpret_cast<const char*>(emb)
                                   + (size_t)hop * N * ROWB;
            for (int c = blockIdx.x; c < CHUNKS; c += gridDim.x) {
                MBAR_WAIT(sb + stage * 16 + 8, phase);
                int base = c * CHUNK;
                int rows = N - base; if (rows > CHUNK) rows = CHUNK;
                uint32_t bytes = (uint32_t)rows * ROWB;
                MBAR_EXPECT_TX(sb + stage * 16, bytes);
                BULK_G2S(sb + SMEM_STAGE0 + stage * STAGE_BYTES,
                         hop_base + (size_t)base * ROWB, bytes, sb + stage * 16);
                if (++stage == STAGES) { stage = 0; phase ^= 1; }
            }
        }
    } else {
        // ------------- consumers: label = warp>>1, half = warp&1 -------------
        const int mylabel = warp >> 1;
        const int half    = warp & 1;          // which 32-node half of the chunk
        const int*       l32 = reinterpret_cast<const int*>(labels_raw);
        const long long* l64 = reinterpret_cast<const long long*>(labels_raw);
        float ax = 0.f, ay = 0.f, az = 0.f, aw = 0.f;
        int cnt = 0;
        int stage = 0, phase = 0;

        for (int c = blockIdx.x; c < CHUNKS; c += gridDim.x) {
            int base = c * CHUNK;
            int rows = N - base; if (rows > CHUNK) rows = CHUNK;

            // this warp's half of the labels (global, L1-hit) — overlaps the bulk copy
            int off = half * 32 + lane;
            int lab = -1;
            if (off < rows)
                lab = is64 ? (int)l64[base + off] : l32[base + off];
            unsigned m = __ballot_sync(0xffffffffu, lab == mylabel);
            cnt += __popc(m);

            MBAR_WAIT(sb + stage * 16, phase);
            eat_mask(m, sb + SMEM_STAGE0 + stage * STAGE_BYTES + half * 32 * ROWB,
                     lane, ax, ay, az, aw);
            __syncwarp();
            if (lane == 0) MBAR_ARRIVE(sb + stage * 16 + 8);
            if (++stage == STAGES) { stage = 0; phase ^= 1; }
        }

        // epilogue: spread REDG (each address hit by 2*GRIDX warps)
        float* dst = &g_sums[hop * LBL * DIM + mylabel * DIM + lane * 4];
        atomicAdd(dst + 0, ax);
        atomicAdd(dst + 1, ay);
        atomicAdd(dst + 2, az);
        atomicAdd(dst + 3, aw);
        if (hop == 0 && lane == 0 && cnt != 0)
            atomicAdd(&g_counts[mylabel], (float)cnt);
    }

    // ---------------- last-block ticket -> finalize + scratch reset ----------
    __threadfence();
    __syncthreads();
    if (tid == 0) s_ticket = atomicAdd(&g_done, 1u);
    __syncthreads();
    if (s_ticket == (unsigned int)(totalBlocks - 1)) {
        for (int i = tid; i < HOPS * LBL * DIM; i += THREADS) {
            int l = (i / DIM) % LBL;
            float c = __ldcg(&g_counts[l]);
            if (c < 1.0f) c = 1.0f;
            out[i] = __ldcg(&g_sums[i]) / c + weight[i];
            g_sums[i] = 0.0f;                       // self-clean for next replay
        }
        if (tid < LBL) {
            out[HOPS * LBL * DIM + tid] = __ldcg(&g_counts[tid]);
            g_counts[tid] = 0.0f;
        }
        __syncthreads();
        if (tid == 0) g_done = 0u;                  // reset ticket last
    }
}

// ---------------------------------------------------------------------------
extern "C" void kernel_launch(void* const* d_in, const int* in_sizes, int n_in,
                              void* d_out, int out_size) {
    const float* emb    = (const float*)d_in[0];   // [3, N, 128] f32
    const void*  labels = d_in[1];                 // [N] int32 or int64
    const float* weight = (const float*)d_in[2];   // [3, 10, 128] f32
    float*       out    = (float*)d_out;           // 3850 f32

    const int N = in_sizes[1];

    static bool attr_set = false;
    if (!attr_set) {
        cudaFuncSetAttribute(accumulate_kernel,
                             cudaFuncAttributeMaxDynamicSharedMemorySize, SMEM_TOTAL);
        attr_set = true;
    }

    dim3 grid(GRIDX, HOPS, 1);
    accumulate_kernel<<<grid, THREADS, SMEM_TOTAL>>>(emb, labels, N, weight, out,
                                                     GRIDX * HOPS);
}

// round 17
// speedup vs baseline: 1.0161x; 1.0161x over previous
#include <cuda_runtime.h>
#include <stdint.h>

#define HOPS   3
#define LBL    10
#define DIM    128
#define ROWB   512                      // bytes per node row (128 f32)
#define CHUNK  64                       // nodes per pipeline stage (32 KB)
#define HALFB  (32 * ROWB)              // 16 KB: stage issued as 2 bulk copies
#define STAGES 3
#define STAGE_BYTES (CHUNK * ROWB)
#define SMEM_STAGE0 1024
#define SMEM_TOTAL  (SMEM_STAGE0 + STAGES * STAGE_BYTES)   // 99328 B -> 2 CTA/SM
#define WARPS  11                       // 10 consumers (1/label) + 1 producer
#define THREADS (WARPS * 32)
#define GRIDX  98                       // per hop; 98*3=294 CTAs = one wave @2 CTA/SM

// Scratch (__device__ globals — zero-initialized at load; the finalizer
// re-zeroes them each run so every graph replay starts from clean scratch).
__device__ float        g_sums[HOPS * LBL * DIM];
__device__ float        g_counts[LBL];
__device__ unsigned int g_done;

// --- PTX helpers -----------------------------------------------------------
__device__ __forceinline__ uint32_t smem_u32(const void* p) {
    uint32_t a;
    asm("{ .reg .u64 t; cvta.to.shared.u64 t, %1; cvt.u32.u64 %0, t; }"
        : "=r"(a) : "l"(p));
    return a;
}
#define MBAR_INIT(addr, cnt) \
    asm volatile("mbarrier.init.shared.b64 [%0], %1;" :: "r"(addr), "r"(cnt) : "memory")
#define MBAR_EXPECT_TX(addr, bytes) \
    asm volatile("mbarrier.arrive.expect_tx.shared.b64 _, [%0], %1;" :: "r"(addr), "r"(bytes) : "memory")
#define MBAR_ARRIVE(addr) \
    asm volatile("mbarrier.arrive.shared.b64 _, [%0];" :: "r"(addr) : "memory")
#define MBAR_WAIT(addr, parity) do {                                          \
    uint32_t _m = (addr); uint32_t _p = (parity); uint32_t _d;                \
    asm volatile("{ .reg .pred p;\n\t"                                        \
        "mbarrier.try_wait.parity.acquire.cta.shared::cta.b64 p, [%1], %2;\n\t"\
        "selp.b32 %0, 1, 0, p; }" : "=r"(_d) : "r"(_m), "r"(_p) : "memory");  \
    if (!_d) {                                                                \
        asm volatile("{ .reg .pred P1;\n\t"                                   \
            "W%=:\n\t"                                                        \
            "mbarrier.try_wait.parity.acquire.cta.shared::cta.b64 P1, [%0], %1, 0x989680;\n\t" \
            "@P1 bra.uni D%=;\n\t"                                            \
            "bra.uni W%=;\n\t"                                                \
            "D%=: }" :: "r"(_m), "r"(_p) : "memory");                         \
    }                                                                         \
} while (0)
// 1D bulk copy global->shared (SASS: UBLKCP), complete_tx to mbarrier.
#define BULK_G2S(dst, src, bytes, mbar) \
    asm volatile("cp.async.bulk.shared::cluster.global.mbarrier::complete_tx::bytes [%0], [%1], %2, [%3];" \
        :: "r"(dst), "l"(src), "r"(bytes), "r"(mbar) : "memory")

__device__ __forceinline__ void lds128(uint32_t a, float& x, float& y, float& z, float& w) {
    asm volatile("ld.shared.v4.f32 {%0,%1,%2,%3}, [%4];"
                 : "=f"(x), "=f"(y), "=f"(z), "=f"(w) : "r"(a));
}

// Consume all set bits of mask: batched LDS.128 row reads + register FADD.
__device__ __forceinline__ void eat_mask(unsigned mask, uint32_t rowbase, int lane,
                                         float& ax, float& ay, float& az, float& aw) {
    while (mask) {
        uint32_t a[4]; int nb = 0;
#pragma unroll
        for (int k = 0; k < 4; k++) {
            if (mask) { int idx = __ffs(mask) - 1; mask &= mask - 1;
                        a[k] = rowbase + idx * ROWB + lane * 16; nb = k + 1; }
        }
        float x[4], y[4], z[4], w[4];
#pragma unroll
        for (int k = 0; k < 4; k++) if (k < nb) lds128(a[k], x[k], y[k], z[k], w[k]);
#pragma unroll
        for (int k = 0; k < 4; k++) if (k < nb) { ax += x[k]; ay += y[k]; az += z[k]; aw += w[k]; }
    }
}

// ---------------------------------------------------------------------------
// Single fused kernel (R15 config; each stage fetched as 2x16 KB bulk copies
// to double per-SM concurrent copy streams). blockIdx.y = hop.
// Warp 10 = producer. Warps 0-9 = per-label consumers.
// Last block (global ticket) finalizes output and re-zeroes scratch.
// ---------------------------------------------------------------------------
__global__ void __launch_bounds__(THREADS, 2)
accumulate_kernel(const float* __restrict__ emb,
                  const void*  __restrict__ labels_raw,
                  int N,
                  const float* __restrict__ weight,
                  float* __restrict__ out,
                  int totalBlocks) {
    extern __shared__ char smem[];
    const uint32_t sb = smem_u32(smem);
    __shared__ int s_not64;
    __shared__ unsigned int s_ticket;

    const int tid  = threadIdx.x;
    const int warp = tid >> 5;
    const int lane = tid & 31;
    const int hop  = blockIdx.y;

    // mbarriers: full(s)=sb+s*16, empty(s)=sb+s*16+8
    if (tid == 0) {
        for (int s = 0; s < STAGES; s++) {
            MBAR_INIT(sb + s * 16,     1u);    // full: tx-based
            MBAR_INIT(sb + s * 16 + 8, 10u);   // empty: 10 consumer warps
        }
        s_not64 = 0;
    }
    __syncthreads();

    // labels dtype detection: int64 labels (0..9, LE) => odd 32-bit words all 0.
    {
        const int* l32 = reinterpret_cast<const int*>(labels_raw);
        int nscan = N / 2; if (nscan > 4096) nscan = 4096;
        for (int j = tid; j < nscan; j += THREADS)
            if (l32[2 * j + 1] != 0) s_not64 = 1;
    }
    __syncthreads();
    const bool is64 = (s_not64 == 0);

    const int CHUNKS = (N + CHUNK - 1) / CHUNK;

    if (warp == 10) {
        // ---------------- producer ----------------
        if (lane == 0) {
            int stage = 0, phase = 1;   // first STAGES empty-waits pass immediately
            const char* hop_base = reinterpret_cast<const char*>(emb)
                                   + (size_t)hop * N * ROWB;
            for (int c = blockIdx.x; c < CHUNKS; c += gridDim.x) {
                MBAR_WAIT(sb + stage * 16 + 8, phase);
                int base = c * CHUNK;
                int rows = N - base; if (rows > CHUNK) rows = CHUNK;
                uint32_t bytes = (uint32_t)rows * ROWB;
                MBAR_EXPECT_TX(sb + stage * 16, bytes);
                // split the stage fetch into 2 concurrent bulk copies
                uint32_t b0 = bytes < HALFB ? bytes : HALFB;
                uint32_t dst = sb + SMEM_STAGE0 + stage * STAGE_BYTES;
                const char* src = hop_base + (size_t)base * ROWB;
                BULK_G2S(dst, src, b0, sb + stage * 16);
                if (bytes > HALFB)
                    BULK_G2S(dst + HALFB, src + HALFB, bytes - HALFB, sb + stage * 16);
                if (++stage == STAGES) { stage = 0; phase ^= 1; }
            }
        }
    } else {
        // ---------------- consumers (one label per warp) ----------------
        const int mylabel = warp;
        const int*       l32 = reinterpret_cast<const int*>(labels_raw);
        const long long* l64 = reinterpret_cast<const long long*>(labels_raw);
        float ax = 0.f, ay = 0.f, az = 0.f, aw = 0.f;
        int cnt = 0;
        int stage = 0, phase = 0;

        for (int c = blockIdx.x; c < CHUNKS; c += gridDim.x) {
            int base = c * CHUNK;
            int rows = N - base; if (rows > CHUNK) rows = CHUNK;

            // labels from global (L1-hit for 9/10 warps) — overlap the bulk copy
            int la = -1, lb = -1;
            if (lane < rows)      la = is64 ? (int)l64[base + lane]      : l32[base + lane];
            if (32 + lane < rows) lb = is64 ? (int)l64[base + 32 + lane] : l32[base + 32 + lane];
            unsigned m0 = __ballot_sync(0xffffffffu, la == mylabel);
            unsigned m1 = __ballot_sync(0xffffffffu, lb == mylabel);
            cnt += __popc(m0) + __popc(m1);

            MBAR_WAIT(sb + stage * 16, phase);
            uint32_t sbase = sb + SMEM_STAGE0 + stage * STAGE_BYTES;
            eat_mask(m0, sbase,         lane, ax, ay, az, aw);
            eat_mask(m1, sbase + HALFB, lane, ax, ay, az, aw);
            __syncwarp();
            if (lane == 0) MBAR_ARRIVE(sb + stage * 16 + 8);
            if (++stage == STAGES) { stage = 0; phase ^= 1; }
        }

        // epilogue: spread REDG (each address hit by GRIDX blocks)
        float* dst = &g_sums[hop * LBL * DIM + mylabel * DIM + lane * 4];
        atomicAdd(dst + 0, ax);
        atomicAdd(dst + 1, ay);
        atomicAdd(dst + 2, az);
        atomicAdd(dst + 3, aw);
        if (hop == 0 && lane == 0 && cnt != 0)
            atomicAdd(&g_counts[mylabel], (float)cnt);
    }

    // ---------------- last-block ticket -> finalize + scratch reset ----------
    __threadfence();
    __syncthreads();
    if (tid == 0) s_ticket = atomicAdd(&g_done, 1u);
    __syncthreads();
    if (s_ticket == (unsigned int)(totalBlocks - 1)) {
        for (int i = tid; i < HOPS * LBL * DIM; i += THREADS) {
            int l = (i / DIM) % LBL;
            float c = __ldcg(&g_counts[l]);
            if (c < 1.0f) c = 1.0f;
            out[i] = __ldcg(&g_sums[i]) / c + weight[i];
            g_sums[i] = 0.0f;                       // self-clean for next replay
        }
        if (tid < LBL) {
            out[HOPS * LBL * DIM + tid] = __ldcg(&g_counts[tid]);
            g_counts[tid] = 0.0f;
        }
        __syncthreads();
        if (tid == 0) g_done = 0u;                  // reset ticket last
    }
}

// ---------------------------------------------------------------------------
extern "C" void kernel_launch(void* const* d_in, const int* in_sizes, int n_in,
                              void* d_out, int out_size) {
    const float* emb    = (const float*)d_in[0];   // [3, N, 128] f32
    const void*  labels = d_in[1];                 // [N] int32 or int64
    const float* weight = (const float*)d_in[2];   // [3, 10, 128] f32
    float*       out    = (float*)d_out;           // 3850 f32

    const int N = in_sizes[1];

    static bool attr_set = false;
    if (!attr_set) {
        cudaFuncSetAttribute(accumulate_kernel,
                             cudaFuncAttributeMaxDynamicSharedMemorySize, SMEM_TOTAL);
        attr_set = true;
    }

    dim3 grid(GRIDX, HOPS, 1);
    accumulate_kernel<<<grid, THREADS, SMEM_TOTAL>>>(emb, labels, N, weight, out,
                                                     GRIDX * HOPS);
}